// round 6
// baseline (speedup 1.0000x reference)
#include <cuda_runtime.h>
#include <float.h>
#include <math.h>

// Problem constants (shapes fixed by the dataset)
#define DIM       256
#define MAXB      128
#define TOPK      32
#define CAND_CAP  65536

#define INV_TAU   10.0f     // 1 / 0.1
#define PEN_COEF  0.25f     // BETA / (2*SIGMA^2) = 0.5 / 2
#define SIM_BOUND 10.0f     // max |q.K| / tau  (q, K unit-norm)

#define QG 32               // queries per logits block
#define CG 64               // candidates per logits chunk
#define PRE_BLOCKS 148      // <= SM count: all resident -> spin barrier is safe
#define P_PARTS 8           // selection parts per query
#define EQCAP 2048          // equal-prefix list capacity (per part)

// ---------------- scratch (device globals; no allocation allowed) ----------
__device__ unsigned int g_ctr;
__device__ unsigned int g_task;
__device__ int          g_count;
__device__ unsigned int g_gmin_bits[32];
__device__ int          g_cidx[CAND_CAP];
__device__ float        g_cpen[CAND_CAP];
__device__ float        g_qn[MAXB * DIM];
__device__ float        g_logits[(size_t)MAXB * CAND_CAP];           // 32 MB
__device__ unsigned long long g_pk[MAXB][P_PARTS * TOPK];            // staging

// order-preserving float <-> uint (descending float == descending uint)
__device__ __forceinline__ unsigned int f2u_ord(float f) {
    unsigned int u = __float_as_uint(f);
    return (u & 0x80000000u) ? ~u : (u | 0x80000000u);
}
__device__ __forceinline__ float u2f_ord(unsigned int u) {
    return (u & 0x80000000u) ? __uint_as_float(u & 0x7FFFFFFFu)
                             : __uint_as_float(~u);
}
// 64-bit selection key: value (ordered) in high bits, ~index low.
// Distinct for distinct (value, index); bigger == better; lower index wins ties.
__device__ __forceinline__ unsigned long long mk_key(float v, int m) {
    return ((unsigned long long)f2u_ord(v) << 32) |
           (unsigned int)(~(unsigned int)m);
}

// packed fp32x2 fma (Blackwell FFMA2 — PTX-only pattern)
__device__ __forceinline__ unsigned long long ffma2(unsigned long long a,
                                                    unsigned long long b,
                                                    unsigned long long c) {
    unsigned long long d;
    asm("fma.rn.f32x2 %0, %1, %2, %3;" : "=l"(d) : "l"(a), "l"(b), "l"(c));
    return d;
}
__device__ __forceinline__ unsigned long long pack2(float lo, float hi) {
    unsigned long long r;
    asm("mov.b64 %0, {%1, %2};" : "=l"(r) : "f"(lo), "f"(hi));
    return r;
}
__device__ __forceinline__ void unpack2(unsigned long long p, float& lo, float& hi) {
    asm("mov.b64 {%0, %1}, %2;" : "=f"(lo), "=f"(hi) : "l"(p));
}

// ---------------------------------------------------------------------------
// Kernel 0: reset counters + per-residue minima.
// ---------------------------------------------------------------------------
__global__ void k_init() {
    if (threadIdx.x == 0) { g_count = 0; g_ctr = 0u; g_task = 0u; }
    if (threadIdx.x < 32) g_gmin_bits[threadIdx.x] = __float_as_uint(FLT_MAX);
}

// ---------------------------------------------------------------------------
// Kernel 1 (fused): query L2-norm + per-residue penalty minima + grid barrier
// + threshold + candidate compaction. Grid = PRE_BLOCKS (all resident).
// Threshold soundness: rows partitioned into 32 disjoint groups by (n mod 32);
// max over the 32 per-group minima >= 32nd-smallest penalty, so
// thresh = bound + 2*SIM_BOUND + margin can never drop a true top-32 row.
// Also guarantees cnt >= 32 (each group's min element passes).
// ---------------------------------------------------------------------------
__global__ void __launch_bounds__(256) k_pre(const float* __restrict__ times,
                                             const float* __restrict__ qtime,
                                             const float* __restrict__ query,
                                             int N, int B) {
    __shared__ float s[256];
    __shared__ float sth;
    int tid = threadIdx.x, bid = blockIdx.x;
    int nb = gridDim.x;

    // --- query L2 normalization (matches F.normalize, eps=1e-12) ---
    if (bid < B) {
        float v = query[bid * DIM + tid];
        s[tid] = v * v;
        __syncthreads();
        #pragma unroll
        for (int st = 128; st > 0; st >>= 1) {
            if (tid < st) s[tid] += s[tid + st];
            __syncthreads();
        }
        float nrm = fmaxf(sqrtf(s[0]), 1e-12f);
        __syncthreads();
        g_qn[bid * DIM + tid] = v / nrm;
    }

    // --- per-residue-group penalty minima ---
    float qt = qtime[0];
    float lmin = FLT_MAX;
    int stride = nb * 256;                 // multiple of 32 -> residue fixed
    for (int n = bid * 256 + tid; n < N; n += stride) {
        float dt = qt - times[n];
        lmin = fminf(lmin, PEN_COEF * dt * dt);
    }
    s[tid] = lmin;
    __syncthreads();
    if (tid < 32) {
        float m = s[tid];
        #pragma unroll
        for (int w = 1; w < 8; w++) m = fminf(m, s[w * 32 + tid]);
        atomicMin(&g_gmin_bits[tid], __float_as_uint(m));
    }
    __syncthreads();

    // --- grid barrier (counter reset by k_init each launch) ---
    if (tid == 0) {
        __threadfence();
        atomicAdd(&g_ctr, 1u);
        while (atomicAdd(&g_ctr, 0u) < (unsigned)nb) __nanosleep(32);
        __threadfence();
        float mx = -FLT_MAX;
        #pragma unroll
        for (int g = 0; g < 32; g++)
            mx = fmaxf(mx, __uint_as_float(g_gmin_bits[g]));
        sth = mx + 2.0f * SIM_BOUND + 4.0f;   // sound bound + fp margin
    }
    __syncthreads();
    float thresh = sth;

    // --- compact candidate rows ---
    for (int n = bid * 256 + tid; n < N; n += stride) {
        float dt = qt - times[n];
        float p = PEN_COEF * dt * dt;
        if (p <= thresh) {
            int pos = atomicAdd(&g_count, 1);
            if (pos < CAND_CAP) { g_cidx[pos] = n; g_cpen[pos] = p; }
        }
    }
}

// ---------------------------------------------------------------------------
// Kernel 2: exact fp32 logits, register-tiled, FFMA2, task-stealing.
// Block tile QG=32 x CG=64, 128 threads, 4x4 register tile held as 8 packed
// f32x2 accumulators. Inner d-step: 2x LDS.128 + 4 pack + 8 FFMA2.
// Tasks = (query group, chunk) pairs pulled from a global atomic counter so
// the 308-over-296 raggedness becomes a 1-chunk tail.
// ---------------------------------------------------------------------------
extern __shared__ float s_dyn[];   // qs[DIM*QG] then kv[DIM*CG]

__global__ void __launch_bounds__(128, 2)
k_logits(const float* __restrict__ Kbank, int B) {
    float* qs = s_dyn;             // [d*QG + q]
    float* kv = s_dyn + DIM * QG;  // [d*CG + c]
    __shared__ float spen[CG];
    __shared__ int s_task;

    int tid = threadIdx.x;
    int cnt = min(g_count, CAND_CAP);
    if (cnt <= 0) return;

    int nch  = (cnt + CG - 1) / CG;
    int ngrp = (B + QG - 1) / QG;
    int ntask = nch * ngrp;

    const float4* qn4 = (const float4*)g_qn;
    const float4* K4  = (const float4*)Kbank;

    int cq = tid & 15, qq = tid >> 4;
    int c0 = cq * 4, q0 = qq * 4;
    int cur_grp = -1;

    for (;;) {
        if (tid == 0) s_task = (int)atomicAdd(&g_task, 1u);
        __syncthreads();                       // also fences kv/qs reuse
        int t = s_task;
        if (t >= ntask) break;
        int grp = t / nch, ch = t - grp * nch;

        if (grp != cur_grp) {
            int q = tid & 31, d4b = tid >> 5;
            int b = grp * QG + q;
            #pragma unroll
            for (int i = 0; i < 16; i++) {
                int d4 = d4b + 4 * i;
                float4 v = (b < B) ? qn4[(size_t)b * (DIM / 4) + d4]
                                   : make_float4(0.f, 0.f, 0.f, 0.f);
                qs[(d4 * 4 + 0) * QG + q] = v.x;
                qs[(d4 * 4 + 1) * QG + q] = v.y;
                qs[(d4 * 4 + 2) * QG + q] = v.z;
                qs[(d4 * 4 + 3) * QG + q] = v.w;
            }
            cur_grp = grp;
        }

        int m0 = ch * CG;
        // ---- load 64 candidate K rows transposed ----
        {
            int c = tid & 63, d4b = tid >> 6;
            int row = g_cidx[min(m0 + c, cnt - 1)];
            #pragma unroll
            for (int i = 0; i < 32; i++) {
                int d4 = d4b + 2 * i;
                float4 v = K4[(size_t)row * (DIM / 4) + d4];
                kv[(d4 * 4 + 0) * CG + c] = v.x;
                kv[(d4 * 4 + 1) * CG + c] = v.y;
                kv[(d4 * 4 + 2) * CG + c] = v.z;
                kv[(d4 * 4 + 3) * CG + c] = v.w;
            }
        }
        if (tid < CG) spen[tid] = g_cpen[min(m0 + tid, cnt - 1)];
        __syncthreads();

        // ---- packed 4x4 register-tile accumulation over d ----
        unsigned long long accp[8];
        #pragma unroll
        for (int i = 0; i < 8; i++) accp[i] = 0ull;

        #pragma unroll 4
        for (int d = 0; d < DIM; d++) {
            ulonglong2 kp = *(const ulonglong2*)&kv[d * CG + c0];  // (c0,c1),(c2,c3)
            float4 qf = *(const float4*)&qs[d * QG + q0];
            unsigned long long qx = pack2(qf.x, qf.x);
            unsigned long long qy = pack2(qf.y, qf.y);
            unsigned long long qz = pack2(qf.z, qf.z);
            unsigned long long qw = pack2(qf.w, qf.w);
            accp[0] = ffma2(qx, kp.x, accp[0]);
            accp[1] = ffma2(qx, kp.y, accp[1]);
            accp[2] = ffma2(qy, kp.x, accp[2]);
            accp[3] = ffma2(qy, kp.y, accp[3]);
            accp[4] = ffma2(qz, kp.x, accp[4]);
            accp[5] = ffma2(qz, kp.y, accp[5]);
            accp[6] = ffma2(qw, kp.x, accp[6]);
            accp[7] = ffma2(qw, kp.y, accp[7]);
        }

        float acc[16];
        #pragma unroll
        for (int qj = 0; qj < 4; qj++) {
            unpack2(accp[qj * 2 + 0], acc[qj * 4 + 0], acc[qj * 4 + 1]);
            unpack2(accp[qj * 2 + 1], acc[qj * 4 + 2], acc[qj * 4 + 3]);
        }

        float p0 = spen[c0 + 0], p1 = spen[c0 + 1];
        float p2 = spen[c0 + 2], p3 = spen[c0 + 3];
        bool full = (m0 + c0 + 3) < cnt;
        #pragma unroll
        for (int qj = 0; qj < 4; qj++) {
            int b = cur_grp * QG + q0 + qj;
            if (b >= B) break;
            float* dst = g_logits + (size_t)b * CAND_CAP + m0 + c0;
            float4 v;
            v.x = acc[qj * 4 + 0] * INV_TAU - p0;
            v.y = acc[qj * 4 + 1] * INV_TAU - p1;
            v.z = acc[qj * 4 + 2] * INV_TAU - p2;
            v.w = acc[qj * 4 + 3] * INV_TAU - p3;
            if (full) {
                *(float4*)dst = v;
            } else {
                float vv[4] = {v.x, v.y, v.z, v.w};
                for (int cj = 0; cj < 4; cj++)
                    if (m0 + c0 + cj < cnt) dst[cj] = vv[cj];
            }
        }
    }
}

// ---------------------------------------------------------------------------
// Kernel 3 (stage 1): per (query, part) EXACT top-32 of the part via radix
// select on 64-bit keys (value||~index). Keys are distinct so the recursion
// terminates exactly; no tie special-casing. Union over parts is a superset
// of the global top-32. Grid (P_PARTS, B), 256 threads.
// ---------------------------------------------------------------------------
__global__ void __launch_bounds__(256) k_sel1(int B) {
    __shared__ unsigned int h0[256], h1[256];
    __shared__ unsigned long long eq[2][EQCAP];
    __shared__ unsigned long long wink[TOPK];
    __shared__ unsigned long long red[8];
    __shared__ int s_nwin, s_neq[2], s_b;

    int p = blockIdx.x, b = blockIdx.y;
    int tid = threadIdx.x, lane = tid & 31, warp = tid >> 5;
    int cnt = min(g_count, CAND_CAP);
    float* grow = g_logits + (size_t)b * CAND_CAP;

    int base = (int)(((long long)cnt * p) / P_PARTS);
    int end  = (int)(((long long)cnt * (p + 1)) / P_PARTS);
    int np = end - base;
    int selk = min(TOPK, np);

    if (tid == 0) { s_nwin = 0; s_neq[0] = 0; s_neq[1] = 0; }
    h0[tid] = 0u;
    __syncthreads();

    if (np > 0 && np <= EQCAP) {
        // ---- level 0: histogram of key byte 7 (gmem pass, warp-agg) ----
        for (int m = base + tid; m < end; m += 256) {
            unsigned int bin = f2u_ord(grow[m]) >> 24;
            unsigned int am = __activemask();
            unsigned int mk = __match_any_sync(am, bin);
            if (lane == __ffs(mk) - 1) atomicAdd(&h0[bin], __popc(mk));
        }
        __syncthreads();
        unsigned int* src = h0; unsigned int* dst = h1;
        #pragma unroll
        for (int off = 1; off < 256; off <<= 1) {
            dst[tid] = src[tid] + ((tid + off < 256) ? src[tid + off] : 0u);
            __syncthreads();
            unsigned int* t = src; src = dst; dst = t;
        }
        {
            unsigned int above = (tid < 255) ? src[tid + 1] : 0u;
            if (src[tid] >= (unsigned)selk && above < (unsigned)selk) s_b = tid;
        }
        __syncthreads();
        int bs = s_b;
        for (int m = base + tid; m < end; m += 256) {
            float v = grow[m];
            unsigned long long key = mk_key(v, m);
            int byt = (int)(key >> 56);
            if (byt > bs) {
                int q = atomicAdd(&s_nwin, 1);
                wink[q] = key;
            } else if (byt == bs) {
                int q = atomicAdd(&s_neq[0], 1);
                eq[0][q] = key;
            }
        }
        __syncthreads();

        // ---- levels 1..7 over the shrinking equals list ----
        int cur = 0;
        for (int lvl = 1; lvl < 8; lvl++) {
            int ne = s_neq[cur];
            int krem = selk - s_nwin;
            if (krem <= 0) break;
            if (ne == krem) {
                for (int i = tid; i < ne; i += 256) {
                    int q = atomicAdd(&s_nwin, 1);
                    wink[q] = eq[cur][i];
                }
                if (tid == 0) s_neq[cur] = 0;
                __syncthreads();
                break;
            }
            int sh = 56 - 8 * lvl;
            h0[tid] = 0u;
            if (tid == 0) s_neq[cur ^ 1] = 0;
            __syncthreads();
            for (int i = tid; i < ne; i += 256) {
                unsigned int bin = (unsigned int)((eq[cur][i] >> sh) & 0xFFull);
                unsigned int am = __activemask();
                unsigned int mk = __match_any_sync(am, bin);
                if (lane == __ffs(mk) - 1) atomicAdd(&h0[bin], __popc(mk));
            }
            __syncthreads();
            src = h0; dst = h1;
            #pragma unroll
            for (int off = 1; off < 256; off <<= 1) {
                dst[tid] = src[tid] + ((tid + off < 256) ? src[tid + off] : 0u);
                __syncthreads();
                unsigned int* t = src; src = dst; dst = t;
            }
            {
                unsigned int above = (tid < 255) ? src[tid + 1] : 0u;
                if (src[tid] >= (unsigned)krem && above < (unsigned)krem) s_b = tid;
            }
            __syncthreads();
            int bsl = s_b;
            for (int i = tid; i < ne; i += 256) {
                unsigned long long key = eq[cur][i];
                int byt = (int)((key >> sh) & 0xFFull);
                if (byt > bsl) {
                    int q = atomicAdd(&s_nwin, 1);
                    wink[q] = key;
                } else if (byt == bsl) {
                    int q = atomicAdd(&s_neq[cur ^ 1], 1);
                    eq[cur ^ 1][q] = key;
                }
            }
            __syncthreads();
            cur ^= 1;
        }
        // ---- final flush (remaining equals == remaining slots) ----
        {
            int krem = selk - s_nwin;
            if (krem > 0) {
                int ne = s_neq[cur];
                for (int i = tid; i < ne; i += 256) {
                    int q = atomicAdd(&s_nwin, 1);
                    if (q < selk) wink[q] = eq[cur][i];
                }
            }
        }
    } else if (np > EQCAP) {
        // ---- fallback (adversarial cnt only): destructive argmax rounds ----
        for (int k = 0; k < selk; k++) {
            unsigned long long best = 0ull;
            for (int m = base + tid; m < end; m += 256) {
                unsigned long long key = mk_key(grow[m], m);
                if (key > best) best = key;
            }
            #pragma unroll
            for (int off = 16; off > 0; off >>= 1) {
                unsigned long long o = __shfl_down_sync(0xFFFFFFFFu, best, off);
                if (o > best) best = o;
            }
            if (lane == 0) red[warp] = best;
            __syncthreads();
            if (tid == 0) {
                unsigned long long bb = red[0];
                #pragma unroll
                for (int w = 1; w < 8; w++) if (red[w] > bb) bb = red[w];
                wink[k] = bb;
                int m = (int)(~(unsigned int)(bb & 0xFFFFFFFFull));
                grow[m] = -FLT_MAX;           // exclude (part range is private)
            }
            __syncthreads();
        }
    }
    __syncthreads();

    // ---- write staging (pad with tiny distinct keys) ----
    if (tid < TOPK) {
        unsigned long long key = (tid < selk)
            ? wink[tid]
            : (unsigned long long)(p * TOPK + tid + 1);
        g_pk[b][p * TOPK + tid] = key;
    }
}

// ---------------------------------------------------------------------------
// Kernel 4 (stage 2): merge P_PARTS*TOPK = 256 staged keys per query by exact
// rank (one key per thread, rank = #larger keys; keys distinct so ranks are a
// permutation), then softmax over the winning 32 + V gather. Grid = B.
// ---------------------------------------------------------------------------
__global__ void __launch_bounds__(256) k_sel2(const float* __restrict__ Vbank,
                                              float* __restrict__ out, int B) {
    __shared__ unsigned long long keys[P_PARTS * TOPK];
    __shared__ float sv[TOPK];
    __shared__ int   si[TOPK];

    int b = blockIdx.x, tid = threadIdx.x;
    keys[tid] = g_pk[b][tid];
    __syncthreads();

    unsigned long long mine = keys[tid];
    int rank = 0;
    #pragma unroll 8
    for (int j = 0; j < P_PARTS * TOPK; j++)
        rank += (keys[j] > mine) ? 1 : 0;
    if (rank < TOPK) {
        sv[rank] = u2f_ord((unsigned int)(mine >> 32));
        si[rank] = (int)(~(unsigned int)(mine & 0xFFFFFFFFull));
    }
    __syncthreads();

    // candidate position -> original row index
    if (tid < TOPK) si[tid] = g_cidx[si[tid]];
    __syncthreads();

    // softmax over the 32 selected logits (order-invariant)
    if (tid < 32) {
        float v = sv[tid];
        float mx = v;
        #pragma unroll
        for (int off = 16; off > 0; off >>= 1)
            mx = fmaxf(mx, __shfl_xor_sync(0xFFFFFFFFu, mx, off));
        float e = expf(v - mx);
        float ssum = e;
        #pragma unroll
        for (int off = 16; off > 0; off >>= 1)
            ssum += __shfl_xor_sync(0xFFFFFFFFu, ssum, off);
        sv[tid] = e / ssum;
    }
    __syncthreads();

    // gather: out[b, d] = sum_k attn[k] * V[idx_k, d]   (tid == d)
    float acc = 0.0f;
    #pragma unroll
    for (int k = 0; k < TOPK; k++)
        acc += sv[k] * Vbank[(size_t)si[k] * DIM + tid];
    out[b * DIM + tid] = acc;
}

// ---------------------------------------------------------------------------
extern "C" void kernel_launch(void* const* d_in, const int* in_sizes, int n_in,
                              void* d_out, int out_size) {
    const float* query = (const float*)d_in[0];
    const float* Kbank = (const float*)d_in[1];
    const float* Vbank = (const float*)d_in[2];
    const float* times = (const float*)d_in[3];
    const float* qtime = (const float*)d_in[4];
    float* out = (float*)d_out;

    int B = in_sizes[0] / DIM;
    int N = in_sizes[3];

    int logits_smem = (DIM * QG + DIM * CG) * (int)sizeof(float);  // 96 KB
    cudaFuncSetAttribute(k_logits, cudaFuncAttributeMaxDynamicSharedMemorySize,
                         logits_smem);

    k_init<<<1, 32>>>();
    k_pre<<<PRE_BLOCKS, 256>>>(times, qtime, query, N, B);
    k_logits<<<296, 128, logits_smem>>>(Kbank, B);   // 2 blocks/SM, task-stealing
    dim3 gs1(P_PARTS, (unsigned)B);
    k_sel1<<<gs1, 256>>>(B);
    k_sel2<<<B, 256>>>(Vbank, out, B);
}